// round 10
// baseline (speedup 1.0000x reference)
#include <cuda_runtime.h>
#include <cuda_bf16.h>
#include <cstdint>

#define N_NODES 100000
#define N_EDGES 1600000
#define F_IN 5
#define F_HID 64
#define F_OUT 72
#define NEG_SLOPE 0.2f

#define EPT 8   // edges per thread in kB/kC (N_EDGES % 8 == 0)

// ---------------- device scratch (static, no allocation) ----------------
__device__ float g_as[N_NODES];       // x[n] . (W @ att_src)
__device__ float g_ad[N_NODES];       // x[n] . (W @ att_dst)
__device__ float g_denom[N_NODES];    // softmax denom per dst (init = self-loop exp)
__device__ float g_selfexp[N_NODES];  // self-loop exp term
__device__ float g_w[N_NODES];        // sum of alpha over edges with src = n
__device__ float g_ex[N_EDGES];       // per-edge exp   (kB -> kC stream)
__device__ int   g_s32[N_EDGES];      // per-edge src32 (kB -> kC stream)
__device__ int   g_d32[N_EDGES];      // per-edge dst32 (kB -> kC stream)
__device__ float g_pool5[F_IN];       // sum_n w_total[n] * x[n, :]
__device__ int   g_idx32;             // 1 if edge_index arrived as int32

// ---------------- Kernel A: per-node attention halves + init ----------------
__global__ void kA(const float* __restrict__ x,
                   const float* __restrict__ W,
                   const float* __restrict__ att_src,
                   const float* __restrict__ att_dst,
                   const void*  __restrict__ ei,
                   const float* __restrict__ W_fc) {
    __shared__ float ws[F_IN], wd[F_IN];
    int tid = threadIdx.x;
    if (tid < F_IN) {
        float s = 0.f, d = 0.f;
#pragma unroll
        for (int f = 0; f < F_HID; f++) {
            float w = W[tid * F_HID + f];
            s += w * att_src[f];
            d += w * att_dst[f];
        }
        ws[tid] = s; wd[tid] = d;
    }
    if (blockIdx.x == 0) {
        if (tid < F_IN) g_pool5[tid] = 0.0f;
        if (tid == 32) {
            // dtype sniff: int32 data read as int64 gives values >= 2^32 or < 0
            const long long* e64 = (const long long*)ei;
            int flag = 0;
            for (int i = 0; i < 64; i++) {
                long long v = e64[i];
                if (v < 0 || v >= (long long)N_NODES) flag = 1;
            }
            g_idx32 = flag;
        }
    }
    if (blockIdx.x == 1) {
        // warm L2 with the FC weights for the tail kernel
        const char* p = (const char*)W_fc;
        int bytes = F_HID * F_OUT * 4;
        for (int off = tid * 128; off < bytes; off += blockDim.x * 128)
            asm volatile("prefetch.global.L2 [%0];" :: "l"(p + off));
    }
    __syncthreads();

    int n = blockIdx.x * blockDim.x + tid;
    if (n >= N_NODES) return;

    const float* xr = x + (size_t)n * F_IN;
    float x0 = xr[0], x1 = xr[1], x2 = xr[2], x3 = xr[3], x4 = xr[4];
    float as = x0*ws[0] + x1*ws[1] + x2*ws[2] + x3*ws[3] + x4*ws[4];
    float ad = x0*wd[0] + x1*wd[1] + x2*wd[2] + x3*wd[3] + x4*wd[4];
    g_as[n] = as;
    g_ad[n] = ad;
    float es = as + ad;
    es = es > 0.0f ? es : NEG_SLOPE * es;   // LeakyReLU
    float se = __expf(es);
    g_denom[n]   = se;                       // denom starts with self-loop term
    g_selfexp[n] = se;
    g_w[n]       = 0.0f;
}

// ---------------- Kernel B: decode edges once, exp -> streams + denom atomics ----------------
__global__ void __launch_bounds__(256)
kB(const void* __restrict__ ei) {
    int e0 = (blockIdx.x * blockDim.x + threadIdx.x) * EPT;
    if (e0 >= N_EDGES) return;
    int s[EPT], d[EPT];
    if (g_idx32) {
        const int* b = (const int*)ei;
#pragma unroll
        for (int q = 0; q < EPT / 4; q++) {
            int4 sv = __ldcs((const int4*)(b + e0 + q * 4));
            int4 dv = __ldcs((const int4*)(b + N_EDGES + e0 + q * 4));
            s[q*4+0] = sv.x; s[q*4+1] = sv.y; s[q*4+2] = sv.z; s[q*4+3] = sv.w;
            d[q*4+0] = dv.x; d[q*4+1] = dv.y; d[q*4+2] = dv.z; d[q*4+3] = dv.w;
        }
    } else {
        const long long* b = (const long long*)ei;
#pragma unroll
        for (int q = 0; q < EPT / 2; q++) {
            ulonglong2 sv = __ldcs((const ulonglong2*)(b + e0 + q * 2));
            ulonglong2 dv = __ldcs((const ulonglong2*)(b + N_EDGES + e0 + q * 2));
            s[q*2+0] = (int)sv.x; s[q*2+1] = (int)sv.y;
            d[q*2+0] = (int)dv.x; d[q*2+1] = (int)dv.y;
        }
    }

    // batch all independent gathers first -> maximum outstanding loads
    float asv[EPT], adv[EPT];
#pragma unroll
    for (int i = 0; i < EPT; i++) asv[i] = g_as[s[i]];
#pragma unroll
    for (int i = 0; i < EPT; i++) adv[i] = g_ad[d[i]];

    float ex[EPT];
#pragma unroll
    for (int i = 0; i < EPT; i++) {
        float ev = asv[i] + adv[i];
        ev = ev > 0.0f ? ev : NEG_SLOPE * ev;
        ex[i] = __expf(ev);
    }
#pragma unroll
    for (int q = 0; q < EPT / 4; q++) {
        *(float4*)&g_ex[e0 + q*4] = make_float4(ex[q*4], ex[q*4+1], ex[q*4+2], ex[q*4+3]);
        *(int4*)&g_s32[e0 + q*4]  = make_int4(s[q*4], s[q*4+1], s[q*4+2], s[q*4+3]);
        *(int4*)&g_d32[e0 + q*4]  = make_int4(d[q*4], d[q*4+1], d[q*4+2], d[q*4+3]);
    }
#pragma unroll
    for (int i = 0; i < EPT; i++) atomicAdd(&g_denom[d[i]], ex[i]);
}

// ---------------- Kernel C: alpha = ex/denom[dst] -> w[src] atomics ----------------
__global__ void __launch_bounds__(256)
kC() {
    int e0 = (blockIdx.x * blockDim.x + threadIdx.x) * EPT;
    if (e0 >= N_EDGES) return;

    int s[EPT], d[EPT];
    float ex[EPT];
#pragma unroll
    for (int q = 0; q < EPT / 4; q++) {
        int4   sv  = __ldcs((const int4*)&g_s32[e0 + q*4]);
        int4   dv  = __ldcs((const int4*)&g_d32[e0 + q*4]);
        float4 exv = __ldcs((const float4*)&g_ex[e0 + q*4]);
        s[q*4+0] = sv.x; s[q*4+1] = sv.y; s[q*4+2] = sv.z; s[q*4+3] = sv.w;
        d[q*4+0] = dv.x; d[q*4+1] = dv.y; d[q*4+2] = dv.z; d[q*4+3] = dv.w;
        ex[q*4+0] = exv.x; ex[q*4+1] = exv.y; ex[q*4+2] = exv.z; ex[q*4+3] = exv.w;
    }

    float dn[EPT];
#pragma unroll
    for (int i = 0; i < EPT; i++) dn[i] = g_denom[d[i]];
#pragma unroll
    for (int i = 0; i < EPT; i++)
        atomicAdd(&g_w[s[i]], ex[i] / (dn[i] + 1e-16f));
}

// ---------------- Kernel D: pool5[k] = sum_n w_total[n] * x[n][k] ----------------
__global__ void kD(const float* __restrict__ x) {
    int n = blockIdx.x * blockDim.x + threadIdx.x;
    float acc[F_IN] = {0.f, 0.f, 0.f, 0.f, 0.f};
    if (n < N_NODES) {
        float wn = g_w[n] + g_selfexp[n] / (g_denom[n] + 1e-16f);
        const float* xr = x + (size_t)n * F_IN;
#pragma unroll
        for (int k = 0; k < F_IN; k++) acc[k] = wn * xr[k];
    }
#pragma unroll
    for (int k = 0; k < F_IN; k++)
#pragma unroll
        for (int o = 16; o > 0; o >>= 1)
            acc[k] += __shfl_xor_sync(0xffffffffu, acc[k], o);

    __shared__ float s[8][F_IN];
    int warp = threadIdx.x >> 5, lane = threadIdx.x & 31;
    if (lane < F_IN) s[warp][lane] = acc[lane];
    __syncthreads();
    if (threadIdx.x < F_IN) {
        float v = 0.f;
#pragma unroll
        for (int wdx = 0; wdx < 8; wdx++) v += s[wdx][threadIdx.x];
        atomicAdd(&g_pool5[threadIdx.x], v);
    }
}

// ---------------- Kernel E: pool5 -> pooled64 -> FC -> ReLU (parallel) ----------------
__global__ void kE(const float* __restrict__ W,
                   const float* __restrict__ b_gat,
                   const float* __restrict__ W_fc,
                   const float* __restrict__ b_fc,
                   float* __restrict__ out) {
    __shared__ float p64[F_HID];
    int t = threadIdx.x;
    if (t < F_HID) {
        float acc = b_gat[t];
        const float invN = 1.0f / (float)N_NODES;
#pragma unroll
        for (int k = 0; k < F_IN; k++)
            acc += (g_pool5[k] * invN) * W[k * F_HID + t];
        p64[t] = acc;
    }
    __syncthreads();

    int o    = t >> 3;            // output index 0..71
    int lane = t & 7;             // 8-lane group
    if (o < F_OUT) {
        float acc = 0.0f;
#pragma unroll
        for (int f = lane; f < F_HID; f += 8)
            acc += p64[f] * W_fc[f * F_OUT + o];
#pragma unroll
        for (int off = 4; off > 0; off >>= 1)
            acc += __shfl_down_sync(0xffffffffu, acc, off, 8);
        if (lane == 0) out[o] = fmaxf(acc + b_fc[o], 0.0f);
    }
}

// ---------------- launch ----------------
extern "C" void kernel_launch(void* const* d_in, const int* in_sizes, int n_in,
                              void* d_out, int out_size) {
    const float* x       = (const float*)d_in[0];
    const void*  ei      = d_in[1];
    const float* W       = (const float*)d_in[2];
    const float* att_src = (const float*)d_in[3];
    const float* att_dst = (const float*)d_in[4];
    const float* b_gat   = (const float*)d_in[5];
    const float* W_fc    = (const float*)d_in[6];
    const float* b_fc    = (const float*)d_in[7];
    float* out = (float*)d_out;

    int blocksN = (N_NODES + 255) / 256;
    int blocksE = (N_EDGES / EPT + 255) / 256;

    kA<<<blocksN, 256>>>(x, W, att_src, att_dst, ei, W_fc);
    kB<<<blocksE, 256>>>(ei);
    kC<<<blocksE, 256>>>();
    kD<<<blocksN, 256>>>(x);
    kE<<<1, 576>>>(W, b_gat, W_fc, b_fc, out);
}

// round 11
// speedup vs baseline: 1.1090x; 1.1090x over previous
#include <cuda_runtime.h>
#include <cuda_bf16.h>
#include <cstdint>

#define N_NODES 100000
#define N_EDGES 1600000
#define F_IN 5
#define F_HID 64
#define F_OUT 72
#define NEG_SLOPE 0.2f

#define EPT 4   // edges per thread (R10 showed 8 regresses: warps > per-thread MLP)

// ---------------- device scratch (static, no allocation) ----------------
__device__ float g_as[N_NODES];       // x[n] . (W @ att_src)
__device__ float g_ad[N_NODES];       // x[n] . (W @ att_dst)
__device__ float g_denom[N_NODES];    // softmax denom per dst (init = self-loop exp)
__device__ float g_selfexp[N_NODES];  // self-loop exp term
__device__ float g_w[N_NODES];        // sum of alpha over edges with src = n
__device__ float g_ex[N_EDGES];       // per-edge exp   (kB -> kC stream)
__device__ int   g_s32[N_EDGES];      // per-edge src32 (kB -> kC stream)
__device__ int   g_d32[N_EDGES];      // per-edge dst32 (kB -> kC stream)
__device__ float g_pool5[F_IN];       // sum_n w_total[n] * x[n, :]

// ---------------- Kernel A: per-node attention halves + init ----------------
__global__ void kA(const float* __restrict__ x,
                   const float* __restrict__ W,
                   const float* __restrict__ att_src,
                   const float* __restrict__ att_dst) {
    __shared__ float ws[F_IN], wd[F_IN];
    int tid = threadIdx.x;
    if (tid < F_IN) {
        float s = 0.f, d = 0.f;
#pragma unroll
        for (int f = 0; f < F_HID; f++) {
            float w = W[tid * F_HID + f];
            s += w * att_src[f];
            d += w * att_dst[f];
        }
        ws[tid] = s; wd[tid] = d;
    }
    if (blockIdx.x == 0 && tid < F_IN) g_pool5[tid] = 0.0f;
    __syncthreads();

    int n = blockIdx.x * blockDim.x + tid;
    if (n < N_NODES) {
        const float* xr = x + (size_t)n * F_IN;
        float x0 = xr[0], x1 = xr[1], x2 = xr[2], x3 = xr[3], x4 = xr[4];
        float as = x0*ws[0] + x1*ws[1] + x2*ws[2] + x3*ws[3] + x4*ws[4];
        float ad = x0*wd[0] + x1*wd[1] + x2*wd[2] + x3*wd[3] + x4*wd[4];
        g_as[n] = as;
        g_ad[n] = ad;
        float es = as + ad;
        es = es > 0.0f ? es : NEG_SLOPE * es;   // LeakyReLU
        float se = __expf(es);
        g_denom[n]   = se;                       // denom starts with self-loop term
        g_selfexp[n] = se;
        g_w[n]       = 0.0f;
    }
#if __CUDA_ARCH__ >= 900
    cudaTriggerProgrammaticLaunchCompletion();
#endif
}

// ---------------- Kernel B: decode edges (pre-sync), exp -> streams + denom atomics ----
__global__ void __launch_bounds__(256)
kB(const void* __restrict__ ei) {
    // local dtype sniff: independent of kA, so it can run pre-sync
    __shared__ int sidx32;
    if (threadIdx.x == 0) {
        const long long* e64 = (const long long*)ei;
        int flag = 0;
        for (int i = 0; i < 64; i++) {
            long long v = e64[i];
            if (v < 0 || v >= (long long)N_NODES) flag = 1;
        }
        sidx32 = flag;
    }
    __syncthreads();

    int e0 = (blockIdx.x * blockDim.x + threadIdx.x) * EPT;
    bool valid = (e0 < N_EDGES);
    int s[EPT], d[EPT];
    if (valid) {
        if (sidx32) {
            const int* b = (const int*)ei;
            int4 sv = __ldcs((const int4*)(b + e0));
            int4 dv = __ldcs((const int4*)(b + N_EDGES + e0));
            s[0] = sv.x; s[1] = sv.y; s[2] = sv.z; s[3] = sv.w;
            d[0] = dv.x; d[1] = dv.y; d[2] = dv.z; d[3] = dv.w;
        } else {
            const long long* b = (const long long*)ei;
            ulonglong2 sa = __ldcs((const ulonglong2*)(b + e0));
            ulonglong2 sb = __ldcs((const ulonglong2*)(b + e0 + 2));
            ulonglong2 da = __ldcs((const ulonglong2*)(b + N_EDGES + e0));
            ulonglong2 db = __ldcs((const ulonglong2*)(b + N_EDGES + e0 + 2));
            s[0] = (int)sa.x; s[1] = (int)sa.y; s[2] = (int)sb.x; s[3] = (int)sb.y;
            d[0] = (int)da.x; d[1] = (int)da.y; d[2] = (int)db.x; d[3] = (int)db.y;
        }
    }

#if __CUDA_ARCH__ >= 900
    cudaGridDependencySynchronize();   // wait for kA's g_as/g_ad/g_denom
#endif

    if (valid) {
        float asv[4], adv[4];
#pragma unroll
        for (int i = 0; i < 4; i++) asv[i] = g_as[s[i]];
#pragma unroll
        for (int i = 0; i < 4; i++) adv[i] = g_ad[d[i]];

        float ex[4];
#pragma unroll
        for (int i = 0; i < 4; i++) {
            float ev = asv[i] + adv[i];
            ev = ev > 0.0f ? ev : NEG_SLOPE * ev;
            ex[i] = __expf(ev);
        }
        *(float4*)&g_ex[e0] = make_float4(ex[0], ex[1], ex[2], ex[3]);
        *(int4*)&g_s32[e0]  = make_int4(s[0], s[1], s[2], s[3]);
        *(int4*)&g_d32[e0]  = make_int4(d[0], d[1], d[2], d[3]);
#pragma unroll
        for (int i = 0; i < 4; i++) atomicAdd(&g_denom[d[i]], ex[i]);
    }
#if __CUDA_ARCH__ >= 900
    cudaTriggerProgrammaticLaunchCompletion();
#endif
}

// ---------------- Kernel C: alpha = ex/denom[dst] -> w[src] atomics ----------------
__global__ void __launch_bounds__(256)
kC() {
    int e0 = (blockIdx.x * blockDim.x + threadIdx.x) * EPT;
#if __CUDA_ARCH__ >= 900
    cudaGridDependencySynchronize();   // all inputs are kB outputs
#endif
    if (e0 < N_EDGES) {
        int4   sv  = __ldcs((const int4*)&g_s32[e0]);
        int4   dv  = __ldcs((const int4*)&g_d32[e0]);
        float4 exv = __ldcs((const float4*)&g_ex[e0]);

        int   s[4]  = {sv.x, sv.y, sv.z, sv.w};
        int   d[4]  = {dv.x, dv.y, dv.z, dv.w};
        float ex[4] = {exv.x, exv.y, exv.z, exv.w};

        float dn[4];
#pragma unroll
        for (int i = 0; i < 4; i++) dn[i] = g_denom[d[i]];
#pragma unroll
        for (int i = 0; i < 4; i++)
            atomicAdd(&g_w[s[i]], ex[i] / (dn[i] + 1e-16f));
    }
#if __CUDA_ARCH__ >= 900
    cudaTriggerProgrammaticLaunchCompletion();
#endif
}

// ---------------- Kernel D: pool5[k] = sum_n w_total[n] * x[n][k] ----------------
__global__ void kD(const float* __restrict__ x) {
    int n = blockIdx.x * blockDim.x + threadIdx.x;
    float xv[F_IN] = {0.f, 0.f, 0.f, 0.f, 0.f};
    if (n < N_NODES) {
        const float* xr = x + (size_t)n * F_IN;   // input-only: pre-sync
#pragma unroll
        for (int k = 0; k < F_IN; k++) xv[k] = xr[k];
    }
#if __CUDA_ARCH__ >= 900
    cudaGridDependencySynchronize();   // wait for kC's g_w
#endif
    float acc[F_IN] = {0.f, 0.f, 0.f, 0.f, 0.f};
    if (n < N_NODES) {
        float wn = g_w[n] + g_selfexp[n] / (g_denom[n] + 1e-16f);
#pragma unroll
        for (int k = 0; k < F_IN; k++) acc[k] = wn * xv[k];
    }
#pragma unroll
    for (int k = 0; k < F_IN; k++)
#pragma unroll
        for (int o = 16; o > 0; o >>= 1)
            acc[k] += __shfl_xor_sync(0xffffffffu, acc[k], o);

    __shared__ float s[8][F_IN];
    int warp = threadIdx.x >> 5, lane = threadIdx.x & 31;
    if (lane < F_IN) s[warp][lane] = acc[lane];
    __syncthreads();
    if (threadIdx.x < F_IN) {
        float v = 0.f;
#pragma unroll
        for (int wdx = 0; wdx < 8; wdx++) v += s[wdx][threadIdx.x];
        atomicAdd(&g_pool5[threadIdx.x], v);
    }
#if __CUDA_ARCH__ >= 900
    cudaTriggerProgrammaticLaunchCompletion();
#endif
}

// ---------------- Kernel E: pool5 -> pooled64 -> FC -> ReLU (parallel) ----------------
// 576 threads = 72 outputs x 8-lane groups. All weights preloaded pre-sync.
__global__ void kE(const float* __restrict__ W,
                   const float* __restrict__ b_gat,
                   const float* __restrict__ W_fc,
                   const float* __restrict__ b_fc,
                   float* __restrict__ out) {
    int t = threadIdx.x;
    int o    = t >> 3;            // output index 0..71
    int lane = t & 7;

    // pre-sync: inputs only
    float wreg[8];
    if (o < F_OUT) {
#pragma unroll
        for (int j = 0; j < 8; j++)
            wreg[j] = W_fc[(lane + 8 * j) * F_OUT + o];
    }
    float wk[F_IN], bg = 0.f;
    if (t < F_HID) {
        bg = b_gat[t];
#pragma unroll
        for (int k = 0; k < F_IN; k++) wk[k] = W[k * F_HID + t];
    }
    float bo = (o < F_OUT && lane == 0) ? b_fc[o] : 0.f;

#if __CUDA_ARCH__ >= 900
    cudaGridDependencySynchronize();   // wait for kD's g_pool5
#endif

    __shared__ float p64[F_HID];
    if (t < F_HID) {
        float acc = bg;
        const float invN = 1.0f / (float)N_NODES;
#pragma unroll
        for (int k = 0; k < F_IN; k++)
            acc += (g_pool5[k] * invN) * wk[k];
        p64[t] = acc;
    }
    __syncthreads();

    if (o < F_OUT) {
        float acc = 0.0f;
#pragma unroll
        for (int j = 0; j < 8; j++)
            acc += p64[lane + 8 * j] * wreg[j];
#pragma unroll
        for (int off = 4; off > 0; off >>= 1)
            acc += __shfl_down_sync(0xffffffffu, acc, off, 8);
        if (lane == 0) out[o] = fmaxf(acc + bo, 0.0f);
    }
}

// ---------------- launch helpers ----------------
template <typename... Args>
static void launch_pdl(void (*kern)(Args...), dim3 grid, dim3 block, Args... args) {
    cudaLaunchConfig_t cfg = {};
    cfg.gridDim = grid;
    cfg.blockDim = block;
    cfg.dynamicSmemBytes = 0;
    cfg.stream = 0;
    cudaLaunchAttribute at[1];
    at[0].id = cudaLaunchAttributeProgrammaticStreamSerialization;
    at[0].val.programmaticStreamSerializationAllowed = 1;
    cfg.attrs = at;
    cfg.numAttrs = 1;
    if (cudaLaunchKernelEx(&cfg, kern, args...) != cudaSuccess) {
        // fallback: plain serialized launch
        kern<<<grid, block>>>(args...);
    }
}

extern "C" void kernel_launch(void* const* d_in, const int* in_sizes, int n_in,
                              void* d_out, int out_size) {
    const float* x       = (const float*)d_in[0];
    const void*  ei      = d_in[1];
    const float* W       = (const float*)d_in[2];
    const float* att_src = (const float*)d_in[3];
    const float* att_dst = (const float*)d_in[4];
    const float* b_gat   = (const float*)d_in[5];
    const float* W_fc    = (const float*)d_in[6];
    const float* b_fc    = (const float*)d_in[7];
    float* out = (float*)d_out;

    dim3 blkN((N_NODES + 255) / 256), thr(256);
    dim3 blkE((N_EDGES / EPT + 255) / 256);

    kA<<<blkN, thr>>>(x, W, att_src, att_dst);
    launch_pdl(kB, blkE, thr, ei);
    launch_pdl(kC, blkE, thr);
    launch_pdl(kD, blkN, thr, x);
    launch_pdl(kE, dim3(1), dim3(576), W, b_gat, W_fc, b_fc, out);
}

// round 16
// speedup vs baseline: 1.1150x; 1.0054x over previous
#include <cuda_runtime.h>
#include <cuda_bf16.h>
#include <cstdint>

#define N_NODES 100000
#define N_EDGES 1600000
#define F_IN 5
#define F_HID 64
#define F_OUT 72
#define NEG_SLOPE 0.2f

#define EPT 4   // edges per thread (R10: EPT=8 regresses; warps beat per-thread MLP)

// ---------------- device scratch (static, no allocation) ----------------
__device__ float g_as[N_NODES];       // x[n] . (W @ att_src)
__device__ float g_ad[N_NODES];       // x[n] . (W @ att_dst)
__device__ float g_denom[N_NODES];    // softmax denom per dst (init = self-loop exp)
__device__ float g_selfexp[N_NODES];  // self-loop exp term
__device__ float g_w[N_NODES];        // sum of alpha over edges with src = n
__device__ float g_ex[N_EDGES];       // per-edge exp   (kB -> kC stream)
__device__ int   g_s32[N_EDGES];      // per-edge src32 (kB -> kC stream)
__device__ int   g_d32[N_EDGES];      // per-edge dst32 (kB -> kC stream)
__device__ float g_pool5[F_IN];       // sum_n w_total[n] * x[n, :]
__device__ int   g_idx32;             // 1 if edge_index arrived as int32

// ---------------- Kernel A: per-node attention halves + init ----------------
__global__ void kA(const float* __restrict__ x,
                   const float* __restrict__ W,
                   const float* __restrict__ att_src,
                   const float* __restrict__ att_dst,
                   const void*  __restrict__ ei,
                   const float* __restrict__ W_fc) {
    __shared__ float ws[F_IN], wd[F_IN];
    int tid = threadIdx.x;
    if (tid < F_IN) {
        float s = 0.f, d = 0.f;
#pragma unroll
        for (int f = 0; f < F_HID; f++) {
            float w = W[tid * F_HID + f];
            s += w * att_src[f];
            d += w * att_dst[f];
        }
        ws[tid] = s; wd[tid] = d;
    }
    if (blockIdx.x == 0) {
        if (tid < F_IN) g_pool5[tid] = 0.0f;
        if (tid == 32) {
            // dtype sniff: int32 data read as int64 gives values >= 2^32 or < 0
            const long long* e64 = (const long long*)ei;
            int flag = 0;
            for (int i = 0; i < 64; i++) {
                long long v = e64[i];
                if (v < 0 || v >= (long long)N_NODES) flag = 1;
            }
            g_idx32 = flag;
        }
    }
    if (blockIdx.x == 1) {
        // warm L2 with the FC weights for the tail kernel
        const char* p = (const char*)W_fc;
        int bytes = F_HID * F_OUT * 4;
        for (int off = tid * 128; off < bytes; off += blockDim.x * 128)
            asm volatile("prefetch.global.L2 [%0];" :: "l"(p + off));
    }
    __syncthreads();

    int n = blockIdx.x * blockDim.x + tid;
    if (n >= N_NODES) return;

    const float* xr = x + (size_t)n * F_IN;
    float x0 = xr[0], x1 = xr[1], x2 = xr[2], x3 = xr[3], x4 = xr[4];
    float as = x0*ws[0] + x1*ws[1] + x2*ws[2] + x3*ws[3] + x4*ws[4];
    float ad = x0*wd[0] + x1*wd[1] + x2*wd[2] + x3*wd[3] + x4*wd[4];
    g_as[n] = as;
    g_ad[n] = ad;
    float es = as + ad;
    es = es > 0.0f ? es : NEG_SLOPE * es;   // LeakyReLU
    float se = __expf(es);
    g_denom[n]   = se;                       // denom starts with self-loop term
    g_selfexp[n] = se;
    g_w[n]       = 0.0f;
}

// ---------------- Kernel B: decode edges once, exp -> streams + denom atomics ----------------
__global__ void __launch_bounds__(256)
kB(const void* __restrict__ ei) {
    int e0 = (blockIdx.x * blockDim.x + threadIdx.x) * EPT;
    if (e0 >= N_EDGES) return;
    int s[4], d[4];
    if (g_idx32) {
        const int* b = (const int*)ei;
        int4 sv = __ldcs((const int4*)(b + e0));
        int4 dv = __ldcs((const int4*)(b + N_EDGES + e0));
        s[0] = sv.x; s[1] = sv.y; s[2] = sv.z; s[3] = sv.w;
        d[0] = dv.x; d[1] = dv.y; d[2] = dv.z; d[3] = dv.w;
    } else {
        const long long* b = (const long long*)ei;
        ulonglong2 sa = __ldcs((const ulonglong2*)(b + e0));
        ulonglong2 sb = __ldcs((const ulonglong2*)(b + e0 + 2));
        ulonglong2 da = __ldcs((const ulonglong2*)(b + N_EDGES + e0));
        ulonglong2 db = __ldcs((const ulonglong2*)(b + N_EDGES + e0 + 2));
        s[0] = (int)sa.x; s[1] = (int)sa.y; s[2] = (int)sb.x; s[3] = (int)sb.y;
        d[0] = (int)da.x; d[1] = (int)da.y; d[2] = (int)db.x; d[3] = (int)db.y;
    }

    // batch independent gathers first -> maximum outstanding loads
    float asv[4], adv[4];
#pragma unroll
    for (int i = 0; i < 4; i++) asv[i] = g_as[s[i]];
#pragma unroll
    for (int i = 0; i < 4; i++) adv[i] = g_ad[d[i]];

    float ex[4];
#pragma unroll
    for (int i = 0; i < 4; i++) {
        float ev = asv[i] + adv[i];
        ev = ev > 0.0f ? ev : NEG_SLOPE * ev;
        ex[i] = __expf(ev);
    }
    *(float4*)&g_ex[e0] = make_float4(ex[0], ex[1], ex[2], ex[3]);
    *(int4*)&g_s32[e0]  = make_int4(s[0], s[1], s[2], s[3]);
    *(int4*)&g_d32[e0]  = make_int4(d[0], d[1], d[2], d[3]);
#pragma unroll
    for (int i = 0; i < 4; i++) atomicAdd(&g_denom[d[i]], ex[i]);
}

// ---------------- Kernel C: alpha = ex/denom[dst] -> w[src] atomics ----------------
__global__ void __launch_bounds__(256)
kC() {
    int e0 = (blockIdx.x * blockDim.x + threadIdx.x) * EPT;
    if (e0 >= N_EDGES) return;

    int4   sv  = __ldcs((const int4*)&g_s32[e0]);
    int4   dv  = __ldcs((const int4*)&g_d32[e0]);
    float4 exv = __ldcs((const float4*)&g_ex[e0]);

    int   s[4]  = {sv.x, sv.y, sv.z, sv.w};
    int   d[4]  = {dv.x, dv.y, dv.z, dv.w};
    float ex[4] = {exv.x, exv.y, exv.z, exv.w};

    float dn[4];
#pragma unroll
    for (int i = 0; i < 4; i++) dn[i] = g_denom[d[i]];
#pragma unroll
    for (int i = 0; i < 4; i++)
        atomicAdd(&g_w[s[i]], ex[i] / (dn[i] + 1e-16f));
}

// ---------------- Kernel D: grid-stride weighted pool (148 blocks = 1/SM) ----------------
#define KD_BLOCKS 148
__global__ void __launch_bounds__(256)
kD(const float* __restrict__ x) {
    float acc[F_IN] = {0.f, 0.f, 0.f, 0.f, 0.f};
    const int stride = KD_BLOCKS * 256;

    for (int n = blockIdx.x * 256 + threadIdx.x; n < N_NODES; n += stride) {
        float wn = g_w[n] + g_selfexp[n] / (g_denom[n] + 1e-16f);
        const float* xr = x + (size_t)n * F_IN;
#pragma unroll
        for (int k = 0; k < F_IN; k++) acc[k] += wn * xr[k];
    }

    // single reduction epilogue per block
#pragma unroll
    for (int k = 0; k < F_IN; k++)
#pragma unroll
        for (int o = 16; o > 0; o >>= 1)
            acc[k] += __shfl_xor_sync(0xffffffffu, acc[k], o);

    __shared__ float s[8][F_IN];
    int warp = threadIdx.x >> 5, lane = threadIdx.x & 31;
    if (lane < F_IN) s[warp][lane] = acc[lane];
    __syncthreads();
    if (threadIdx.x < F_IN) {
        float v = 0.f;
#pragma unroll
        for (int wdx = 0; wdx < 8; wdx++) v += s[wdx][threadIdx.x];
        atomicAdd(&g_pool5[threadIdx.x], v);
    }
}

// ---------------- Kernel E: pool5 -> pooled64 -> FC -> ReLU (parallel) ----------------
// 576 threads = 72 outputs x 8-lane dot-product groups.
__global__ void kE(const float* __restrict__ W,
                   const float* __restrict__ b_gat,
                   const float* __restrict__ W_fc,
                   const float* __restrict__ b_fc,
                   float* __restrict__ out) {
    __shared__ float p64[F_HID];
    int t = threadIdx.x;
    if (t < F_HID) {
        float acc = b_gat[t];
        const float invN = 1.0f / (float)N_NODES;
#pragma unroll
        for (int k = 0; k < F_IN; k++)
            acc += (g_pool5[k] * invN) * W[k * F_HID + t];
        p64[t] = acc;
    }
    __syncthreads();

    int o    = t >> 3;            // output index 0..71
    int lane = t & 7;             // 8-lane group
    if (o < F_OUT) {
        float acc = 0.0f;
#pragma unroll
        for (int f = lane; f < F_HID; f += 8)
            acc += p64[f] * W_fc[f * F_OUT + o];
#pragma unroll
        for (int off = 4; off > 0; off >>= 1)
            acc += __shfl_down_sync(0xffffffffu, acc, off, 8);
        if (lane == 0) out[o] = fmaxf(acc + b_fc[o], 0.0f);
    }
}

// ---------------- launch ----------------
extern "C" void kernel_launch(void* const* d_in, const int* in_sizes, int n_in,
                              void* d_out, int out_size) {
    const float* x       = (const float*)d_in[0];
    const void*  ei      = d_in[1];
    const float* W       = (const float*)d_in[2];
    const float* att_src = (const float*)d_in[3];
    const float* att_dst = (const float*)d_in[4];
    const float* b_gat   = (const float*)d_in[5];
    const float* W_fc    = (const float*)d_in[6];
    const float* b_fc    = (const float*)d_in[7];
    float* out = (float*)d_out;

    int blocksN = (N_NODES + 255) / 256;
    int blocksE = (N_EDGES / EPT + 255) / 256;

    kA<<<blocksN, 256>>>(x, W, att_src, att_dst, ei, W_fc);
    kB<<<blocksE, 256>>>(ei);
    kC<<<blocksE, 256>>>();
    kD<<<KD_BLOCKS, 256>>>(x);
    kE<<<1, 576>>>(W, b_gat, W_fc, b_fc, out);
}

// round 17
// speedup vs baseline: 1.1651x; 1.0450x over previous
#include <cuda_runtime.h>
#include <cuda_fp16.h>
#include <cuda_bf16.h>
#include <cstdint>

#define N_NODES 100000
#define N_EDGES 1600000
#define F_IN 5
#define F_HID 64
#define F_OUT 72
#define NEG_SLOPE 0.2f

#define EPT 4   // edges per thread (tuned: 8 regresses)

// ---------------- device scratch (static, no allocation) ----------------
__device__ __half2 g_att[N_NODES];    // {as, ad} packed half2 -> 400KB... no: 4B*100k = 400KB? (4 bytes each) = 400KB
// NOTE: __half2 = 4 bytes -> table is 400KB. Split tables would be 2x200KB but
// need two gathers anyway; packed keeps ONE table so both kB gathers hit the
// same 400KB working set. L1=228KB holds ~57%: partial residency, still a big
// cut vs 800KB fp32. (If this under-delivers, next step is separate half
// tables at 200KB each.)
__device__ float   g_denom[N_NODES];  // softmax denom per dst (init = self-loop exp)
__device__ float   g_selfexp[N_NODES];// self-loop exp term
__device__ float   g_w[N_NODES];      // sum of alpha over edges with src = n
__device__ __half  g_dinv[N_NODES];   // half(1/(denom+eps)) -> 200KB, L1-resident in kC
__device__ float   g_wself[N_NODES];  // selfexp/denom (fp32)
__device__ float   g_ex[N_EDGES];     // per-edge exp   (kB -> kC stream)
__device__ int     g_s32[N_EDGES];    // per-edge src32 (kB -> kC stream)
__device__ int     g_d32[N_EDGES];    // per-edge dst32 (kB -> kC stream)
__device__ float   g_pool5[F_IN];     // sum_n w_total[n] * x[n, :]
__device__ int     g_idx32;           // 1 if edge_index arrived as int32

// ---------------- Kernel A: per-node attention halves + init ----------------
__global__ void kA(const float* __restrict__ x,
                   const float* __restrict__ W,
                   const float* __restrict__ att_src,
                   const float* __restrict__ att_dst,
                   const void*  __restrict__ ei,
                   const float* __restrict__ W_fc) {
    __shared__ float ws[F_IN], wd[F_IN];
    int tid = threadIdx.x;
    if (tid < F_IN) {
        float s = 0.f, d = 0.f;
#pragma unroll
        for (int f = 0; f < F_HID; f++) {
            float w = W[tid * F_HID + f];
            s += w * att_src[f];
            d += w * att_dst[f];
        }
        ws[tid] = s; wd[tid] = d;
    }
    if (blockIdx.x == 0) {
        if (tid < F_IN) g_pool5[tid] = 0.0f;
        if (tid == 32) {
            // dtype sniff: int32 data read as int64 gives values >= 2^32 or < 0
            const long long* e64 = (const long long*)ei;
            int flag = 0;
            for (int i = 0; i < 64; i++) {
                long long v = e64[i];
                if (v < 0 || v >= (long long)N_NODES) flag = 1;
            }
            g_idx32 = flag;
        }
    }
    if (blockIdx.x == 1) {
        // warm L2 with the FC weights for the tail kernel
        const char* p = (const char*)W_fc;
        int bytes = F_HID * F_OUT * 4;
        for (int off = tid * 128; off < bytes; off += blockDim.x * 128)
            asm volatile("prefetch.global.L2 [%0];" :: "l"(p + off));
    }
    __syncthreads();

    int n = blockIdx.x * blockDim.x + tid;
    if (n >= N_NODES) return;

    const float* xr = x + (size_t)n * F_IN;
    float x0 = xr[0], x1 = xr[1], x2 = xr[2], x3 = xr[3], x4 = xr[4];
    float as = x0*ws[0] + x1*ws[1] + x2*ws[2] + x3*ws[3] + x4*ws[4];
    float ad = x0*wd[0] + x1*wd[1] + x2*wd[2] + x3*wd[3] + x4*wd[4];
    g_att[n] = __floats2half2_rn(as, ad);    // low = as, high = ad

    // self-loop term computed from the SAME half-rounded values the edge path
    // sees, so numerator/denominator quantization errors stay correlated.
    float ash = __half2float(__float2half_rn(as));
    float adh = __half2float(__float2half_rn(ad));
    float es = ash + adh;
    es = es > 0.0f ? es : NEG_SLOPE * es;    // LeakyReLU
    float se = __expf(es);
    g_denom[n]   = se;                        // denom starts with self-loop term
    g_selfexp[n] = se;
    g_w[n]       = 0.0f;
}

// ---------------- Kernel B: decode edges once, half2-gather exp -> streams + denom RED ----
__global__ void __launch_bounds__(256)
kB(const void* __restrict__ ei) {
    int e0 = (blockIdx.x * blockDim.x + threadIdx.x) * EPT;
    if (e0 >= N_EDGES) return;
    int s[4], d[4];
    if (g_idx32) {
        const int* b = (const int*)ei;
        int4 sv = __ldcs((const int4*)(b + e0));
        int4 dv = __ldcs((const int4*)(b + N_EDGES + e0));
        s[0] = sv.x; s[1] = sv.y; s[2] = sv.z; s[3] = sv.w;
        d[0] = dv.x; d[1] = dv.y; d[2] = dv.z; d[3] = dv.w;
    } else {
        const long long* b = (const long long*)ei;
        ulonglong2 sa = __ldcs((const ulonglong2*)(b + e0));
        ulonglong2 sb = __ldcs((const ulonglong2*)(b + e0 + 2));
        ulonglong2 da = __ldcs((const ulonglong2*)(b + N_EDGES + e0));
        ulonglong2 db = __ldcs((const ulonglong2*)(b + N_EDGES + e0 + 2));
        s[0] = (int)sa.x; s[1] = (int)sa.y; s[2] = (int)sb.x; s[3] = (int)sb.y;
        d[0] = (int)da.x; d[1] = (int)da.y; d[2] = (int)db.x; d[3] = (int)db.y;
    }

    // batch independent gathers (L1-cached half2 table)
    __half2 ps[4], pd[4];
#pragma unroll
    for (int i = 0; i < 4; i++) ps[i] = g_att[s[i]];
#pragma unroll
    for (int i = 0; i < 4; i++) pd[i] = g_att[d[i]];

    float ex[4];
#pragma unroll
    for (int i = 0; i < 4; i++) {
        float ev = __low2float(ps[i]) + __high2float(pd[i]);
        ev = ev > 0.0f ? ev : NEG_SLOPE * ev;
        ex[i] = __expf(ev);
    }
    *(float4*)&g_ex[e0] = make_float4(ex[0], ex[1], ex[2], ex[3]);
    *(int4*)&g_s32[e0]  = make_int4(s[0], s[1], s[2], s[3]);
    *(int4*)&g_d32[e0]  = make_int4(d[0], d[1], d[2], d[3]);
#pragma unroll
    for (int i = 0; i < 4; i++) atomicAdd(&g_denom[d[i]], ex[i]);
}

// ---------------- Kernel N: denom -> half inverse table + fp32 self-weight ----------------
__global__ void kN() {
    int n = blockIdx.x * blockDim.x + threadIdx.x;
    if (n >= N_NODES) return;
    float inv = 1.0f / (g_denom[n] + 1e-16f);
    g_dinv[n]  = __float2half_rn(inv);
    g_wself[n] = g_selfexp[n] * inv;
}

// ---------------- Kernel C: alpha = ex * dinv[dst] -> w[src] RED ----------------
__global__ void __launch_bounds__(256)
kC() {
    int e0 = (blockIdx.x * blockDim.x + threadIdx.x) * EPT;
    if (e0 >= N_EDGES) return;

    int4   sv  = __ldcs((const int4*)&g_s32[e0]);
    int4   dv  = __ldcs((const int4*)&g_d32[e0]);
    float4 exv = __ldcs((const float4*)&g_ex[e0]);

    int   s[4]  = {sv.x, sv.y, sv.z, sv.w};
    int   d[4]  = {dv.x, dv.y, dv.z, dv.w};
    float ex[4] = {exv.x, exv.y, exv.z, exv.w};

    // L1-resident 200KB half table
    float dn[4];
#pragma unroll
    for (int i = 0; i < 4; i++) dn[i] = __half2float(g_dinv[d[i]]);
#pragma unroll
    for (int i = 0; i < 4; i++)
        atomicAdd(&g_w[s[i]], ex[i] * dn[i]);
}

// ---------------- Kernel D: pool5[k] = sum_n w_total[n] * x[n][k] ----------------
__global__ void kD(const float* __restrict__ x) {
    int n = blockIdx.x * blockDim.x + threadIdx.x;
    float acc[F_IN] = {0.f, 0.f, 0.f, 0.f, 0.f};
    if (n < N_NODES) {
        float wn = g_w[n] + g_wself[n];
        const float* xr = x + (size_t)n * F_IN;
#pragma unroll
        for (int k = 0; k < F_IN; k++) acc[k] = wn * xr[k];
    }
#pragma unroll
    for (int k = 0; k < F_IN; k++)
#pragma unroll
        for (int o = 16; o > 0; o >>= 1)
            acc[k] += __shfl_xor_sync(0xffffffffu, acc[k], o);

    __shared__ float s[8][F_IN];
    int warp = threadIdx.x >> 5, lane = threadIdx.x & 31;
    if (lane < F_IN) s[warp][lane] = acc[lane];
    __syncthreads();
    if (threadIdx.x < F_IN) {
        float v = 0.f;
#pragma unroll
        for (int wdx = 0; wdx < 8; wdx++) v += s[wdx][threadIdx.x];
        atomicAdd(&g_pool5[threadIdx.x], v);
    }
}

// ---------------- Kernel E: pool5 -> pooled64 -> FC -> ReLU (parallel) ----------------
__global__ void kE(const float* __restrict__ W,
                   const float* __restrict__ b_gat,
                   const float* __restrict__ W_fc,
                   const float* __restrict__ b_fc,
                   float* __restrict__ out) {
    __shared__ float p64[F_HID];
    int t = threadIdx.x;
    if (t < F_HID) {
        float acc = b_gat[t];
        const float invN = 1.0f / (float)N_NODES;
#pragma unroll
        for (int k = 0; k < F_IN; k++)
            acc += (g_pool5[k] * invN) * W[k * F_HID + t];
        p64[t] = acc;
    }
    __syncthreads();

    int o    = t >> 3;            // output index 0..71
    int lane = t & 7;             // 8-lane group
    if (o < F_OUT) {
        float acc = 0.0f;
#pragma unroll
        for (int f = lane; f < F_HID; f += 8)
            acc += p64[f] * W_fc[f * F_OUT + o];
#pragma unroll
        for (int off = 4; off > 0; off >>= 1)
            acc += __shfl_down_sync(0xffffffffu, acc, off, 8);
        if (lane == 0) out[o] = fmaxf(acc + b_fc[o], 0.0f);
    }
}

// ---------------- launch ----------------
extern "C" void kernel_launch(void* const* d_in, const int* in_sizes, int n_in,
                              void* d_out, int out_size) {
    const float* x       = (const float*)d_in[0];
    const void*  ei      = d_in[1];
    const float* W       = (const float*)d_in[2];
    const float* att_src = (const float*)d_in[3];
    const float* att_dst = (const float*)d_in[4];
    const float* b_gat   = (const float*)d_in[5];
    const float* W_fc    = (const float*)d_in[6];
    const float* b_fc    = (const float*)d_in[7];
    float* out = (float*)d_out;

    int blocksN = (N_NODES + 255) / 256;
    int blocksE = (N_EDGES / EPT + 255) / 256;

    kA<<<blocksN, 256>>>(x, W, att_src, att_dst, ei, W_fc);
    kB<<<blocksE, 256>>>(ei);
    kN<<<blocksN, 256>>>();
    kC<<<blocksE, 256>>>();
    kD<<<blocksN, 256>>>(x);
    kE<<<1, 576>>>(W, b_gat, W_fc, b_fc, out);
}